// round 2
// baseline (speedup 1.0000x reference)
#include <cuda_runtime.h>

#define KSZ   2
#define CIN   3
#define COUT  16
#define HIN   256
#define WIN   256
#define HF    255
#define WF    255
#define HO    254
#define WO    254
#define BATCH 64
#define NPIX  (BATCH * HF * WF)
#define BN_EPS 1e-5f

typedef unsigned long long u64;

// ---------------- packed f32x2 helpers (sm_100+) ----------------
__device__ __forceinline__ u64 pk2(float lo, float hi) {
    u64 r; asm("mov.b64 %0,{%1,%2};" : "=l"(r) : "f"(lo), "f"(hi)); return r;
}
__device__ __forceinline__ void up2(u64 v, float& lo, float& hi) {
    asm("mov.b64 {%0,%1},%2;" : "=f"(lo), "=f"(hi) : "l"(v));
}
__device__ __forceinline__ u64 fma2(u64 a, u64 b, u64 c) {
    u64 d; asm("fma.rn.f32x2 %0,%1,%2,%3;" : "=l"(d) : "l"(a), "l"(b), "l"(c)); return d;
}
__device__ __forceinline__ u64 mul2(u64 a, u64 b) {
    u64 d; asm("mul.rn.f32x2 %0,%1,%2;" : "=l"(d) : "l"(a), "l"(b)); return d;
}
__device__ __forceinline__ u64 add2(u64 a, u64 b) {
    u64 d; asm("add.rn.f32x2 %0,%1,%2;" : "=l"(d) : "l"(a), "l"(b)); return d;
}
__device__ __forceinline__ float tha(float x) {
    float y; asm("tanh.approx.f32 %0,%1;" : "=f"(y) : "f"(x)); return y;
}

// ---------------- device scratch (no allocations allowed) ----------------
__device__ u64    g_wp[COUT * 12];   // packed replicated conv weights
__device__ double g_acc[2 * COUT];   // sum / sumsq of conv outputs
__device__ u64    g_post[2 * COUT];  // [0..15] packed scale, [16..31] packed shift

// ---------------------------------------------------------------------------
// Kernel 0: replicate weights into packed doubles + zero accumulators
// ---------------------------------------------------------------------------
__global__ void prep_kernel(const float* __restrict__ w) {
    int t = threadIdx.x;
    if (t < COUT * 12) { float v = w[t]; g_wp[t] = pk2(v, v); }
    if (t < 2 * COUT) g_acc[t] = 0.0;
}

// ---------------------------------------------------------------------------
// Kernel 1: per-channel sum/sumsq of bias-free conv, packed pixel pairs.
// Item = (b, i, jp) with j = 2*jp, jp in [0,128). Pair (254,255): hi masked 0.
// ---------------------------------------------------------------------------
#define NITEM (BATCH * HF * 128)

__global__ void __launch_bounds__(256) stats_kernel(const float* __restrict__ x) {
    __shared__ u64 sw[COUT * 12];
    for (int i = threadIdx.x; i < COUT * 12; i += 256) sw[i] = g_wp[i];
    __syncthreads();

    u64 s2[COUT], q2[COUT];
#pragma unroll
    for (int c = 0; c < COUT; c++) { s2[c] = 0ull; q2[c] = 0ull; }

    const int stride = gridDim.x * blockDim.x;
    for (int idx = blockIdx.x * blockDim.x + threadIdx.x; idx < NITEM; idx += stride) {
        const int b   = idx / (HF * 128);
        const int rem = idx % (HF * 128);
        const int i   = rem >> 7;
        const int j   = (rem & 127) << 1;
        const bool edge = (j == 254);
        const float* xb = x + (size_t)b * CIN * HIN * WIN + (size_t)i * WIN + j;

        u64 t[12];
#pragma unroll
        for (int ci = 0; ci < CIN; ci++) {
            const float* p = xb + ci * HIN * WIN;
            u64 a0 = *(const u64*)p;
            u64 a1 = *(const u64*)(p + WIN);
            float a0lo, a0hi, a1lo, a1hi;
            up2(a0, a0lo, a0hi); up2(a1, a1lo, a1hi);
            float c0 = 0.f, c1 = 0.f;
            if (!edge) { c0 = p[2]; c1 = p[2 + WIN]; a0lo = a0lo; }
            if (edge)  { a0hi = 0.f; a1hi = 0.f; }
            t[ci * 4 + 0] = pk2(a0lo, a0hi);
            t[ci * 4 + 1] = pk2(a0hi, c0);
            t[ci * 4 + 2] = pk2(a1lo, a1hi);
            t[ci * 4 + 3] = pk2(a1hi, c1);
        }
#pragma unroll
        for (int c = 0; c < COUT; c++) {
            u64 v = mul2(sw[c * 12], t[0]);
#pragma unroll
            for (int k = 1; k < 12; k++) v = fma2(sw[c * 12 + k], t[k], v);
            s2[c] = add2(s2[c], v);
            q2[c] = fma2(v, v, q2[c]);
        }
    }

    // collapse packed halves, warp reduce, block reduce, atomics
    float s[COUT], q[COUT];
#pragma unroll
    for (int c = 0; c < COUT; c++) {
        float a, b2; up2(s2[c], a, b2); s[c] = a + b2;
        up2(q2[c], a, b2); q[c] = a + b2;
    }
    const unsigned m = 0xffffffffu;
#pragma unroll
    for (int c = 0; c < COUT; c++) {
        float a = s[c];
#pragma unroll
        for (int o = 16; o > 0; o >>= 1) a += __shfl_xor_sync(m, a, o);
        s[c] = a;
        float b2 = q[c];
#pragma unroll
        for (int o = 16; o > 0; o >>= 1) b2 += __shfl_xor_sync(m, b2, o);
        q[c] = b2;
    }
    __shared__ float sred[8][32];
    const int warp = threadIdx.x >> 5, lane = threadIdx.x & 31;
    if (lane == 0) {
#pragma unroll
        for (int c = 0; c < COUT; c++) { sred[warp][c] = s[c]; sred[warp][16 + c] = q[c]; }
    }
    __syncthreads();
    if (threadIdx.x < 32) {
        float tot = 0.f;
        for (int w = 0; w < 8; w++) tot += sred[w][threadIdx.x];
        atomicAdd(&g_acc[threadIdx.x], (double)tot);
    }
}

// ---------------------------------------------------------------------------
// Kernel 2: fold BN into packed per-channel scale/shift (conv bias cancels)
// ---------------------------------------------------------------------------
__global__ void finalize_kernel(const float* __restrict__ gamma,
                                const float* __restrict__ beta) {
    int c = threadIdx.x;
    if (c >= COUT) return;
    const double N = (double)NPIX;
    double mean = g_acc[c] / N;
    double var  = g_acc[COUT + c] / N - mean * mean;
    float scale = gamma[c] * rsqrtf((float)var + BN_EPS);
    float shift = beta[c] - (float)mean * scale;
    g_post[c]        = pk2(scale, scale);
    g_post[COUT + c] = pk2(shift, shift);
}

// ---------------------------------------------------------------------------
// Kernel 3: fused conv+BN+relu+tanh+channel-sum+2x2 mean.
// Block: 256 threads, output tile 32x14. Feat tile 34x15 via 17 packed pairs
// x 15 rows = 255 one-item threads. x tile 35x16 per input channel in smem.
// ---------------------------------------------------------------------------
__global__ void __launch_bounds__(256) fused_out_kernel(const float* __restrict__ x,
                                                        float* __restrict__ out) {
    __shared__ __align__(16) float sx[CIN][16][36];
    __shared__ __align__(16) float st[15][36];
    __shared__ u64 sw[COUT * 12];
    __shared__ u64 ssc[COUT], ssh[COUT];

    const int tid = threadIdx.x;
    const int b   = blockIdx.z;
    const int oy0 = blockIdx.y * 14;
    const int ox0 = blockIdx.x * 32;

    for (int i = tid; i < COUT * 12; i += 256) sw[i] = g_wp[i];
    if (tid < COUT) { ssc[tid] = g_post[tid]; ssh[tid] = g_post[COUT + tid]; }

    const float* xb = x + (size_t)b * CIN * HIN * WIN;
    for (int idx = tid; idx < CIN * 16 * 35; idx += 256) {
        const int col = idx % 35;
        const int t2  = idx / 35;
        const int r   = t2 & 15;
        const int ci  = t2 >> 4;
        const int gr = oy0 + r, gc = ox0 + col;
        float v = 0.f;
        if (gr < HIN && gc < WIN) v = __ldg(&xb[(ci * HIN + gr) * WIN + gc]);
        sx[ci][r][col] = v;
    }
    __syncthreads();

    if (tid < 255) {
        const int fy = tid / 17;       // 0..14
        const int px = tid % 17;       // 0..16
        const int fx = px * 2;         // 0..32 (even)

        u64 t[12];
#pragma unroll
        for (int ci = 0; ci < CIN; ci++) {
            const float* p0 = &sx[ci][fy][fx];
            const float* p1 = &sx[ci][fy + 1][fx];
            u64 a0 = *(const u64*)p0; float c0 = p0[2];
            u64 a1 = *(const u64*)p1; float c1 = p1[2];
            float a0lo, a0hi, a1lo, a1hi;
            up2(a0, a0lo, a0hi); up2(a1, a1lo, a1hi);
            t[ci * 4 + 0] = a0;
            t[ci * 4 + 1] = pk2(a0hi, c0);
            t[ci * 4 + 2] = a1;
            t[ci * 4 + 3] = pk2(a1hi, c1);
        }

        float accA = 0.f, accB = 0.f;
#pragma unroll
        for (int c = 0; c < COUT; c++) {
            u64 v = mul2(sw[c * 12], t[0]);
#pragma unroll
            for (int k = 1; k < 12; k++) v = fma2(sw[c * 12 + k], t[k], v);
            v = fma2(v, ssc[c], ssh[c]);            // BN scale+shift, packed
            float lo, hi; up2(v, lo, hi);
            accA += tha(fmaxf(lo, 0.f));            // relu + tanh.approx (MUFU)
            accB += tha(fmaxf(hi, 0.f));
        }
        *(u64*)&st[fy][fx] = pk2(accA, accB);
    }
    __syncthreads();

    const float inv = 1.0f / (COUT * KSZ * KSZ);
    const int tx = tid & 31, ty = tid >> 5;
#pragma unroll
    for (int rr = 0; rr < 2; rr++) {
        const int oy = ty + rr * 8;
        const int oi = oy0 + oy, oj = ox0 + tx;
        if (oy < 14 && oi < HO && oj < WO) {
            const float r = (st[oy][tx] + st[oy][tx + 1] +
                             st[oy + 1][tx] + st[oy + 1][tx + 1]) * inv;
            out[((size_t)b * HO + oi) * WO + oj] = r;
        }
    }
}

// ---------------------------------------------------------------------------
// kernel_launch: inputs: x, conv_w, conv_b (cancels under BN), gamma, beta
// ---------------------------------------------------------------------------
extern "C" void kernel_launch(void* const* d_in, const int* in_sizes, int n_in,
                              void* d_out, int out_size) {
    const float* x      = (const float*)d_in[0];
    const float* conv_w = (const float*)d_in[1];
    const float* gamma  = (const float*)d_in[3];
    const float* beta   = (const float*)d_in[4];
    float* out = (float*)d_out;

    prep_kernel<<<1, 192>>>(conv_w);
    stats_kernel<<<1184, 256>>>(x);
    finalize_kernel<<<1, COUT>>>(gamma, beta);

    dim3 grid((WO + 31) / 32, (HO + 13) / 14, BATCH);   // 8 x 19 x 64
    fused_out_kernel<<<grid, 256>>>(x, out);
}

// round 3
// speedup vs baseline: 2.2378x; 2.2378x over previous
#include <cuda_runtime.h>

#define KSZ   2
#define CIN   3
#define COUT  16
#define HIN   256
#define WIN   256
#define HF    255
#define WF    255
#define HO    254
#define WO    254
#define BATCH 64
#define NPIX  (BATCH * HF * WF)
#define BN_EPS 1e-5f

#define NTAP  12            // 3 ci * 2 * 2 taps
#define NTRI  78            // NTAP*(NTAP+1)/2
#define NSTAT (NTAP + NTRI) // 90

// ---------------- device scratch (no allocation allowed) ----------------
__device__ double g_stat[NSTAT];   // [0..11] tap sums S, [12..89] Gram lower-tri
__device__ float  g_scale[COUT];
__device__ float  g_shift[COUT];

__device__ __forceinline__ float tha(float x) {
    float y; asm("tanh.approx.f32 %0,%1;" : "=f"(y) : "f"(x)); return y;
}

// ---------------------------------------------------------------------------
// Kernel 0: zero statistics accumulators (graph replays reuse them)
// ---------------------------------------------------------------------------
__global__ void prep_kernel() {
    int t = threadIdx.x;
    if (t < NSTAT) g_stat[t] = 0.0;
}

// ---------------------------------------------------------------------------
// Kernel 1: channel-independent tap sums + Gram matrix.
// S_k = sum_pix tap_k ; G_kl = sum_pix tap_k*tap_l (lower triangle).
// ---------------------------------------------------------------------------
__global__ void __launch_bounds__(256, 1) stats_kernel(const float* __restrict__ x) {
    float S[NTAP];
    float G[NTRI];
#pragma unroll
    for (int k = 0; k < NTAP; k++) S[k] = 0.f;
#pragma unroll
    for (int k = 0; k < NTRI; k++) G[k] = 0.f;

    const int stride = gridDim.x * blockDim.x;
    for (int idx = blockIdx.x * blockDim.x + threadIdx.x; idx < NPIX; idx += stride) {
        const int b   = idx / (HF * WF);
        const int rem = idx % (HF * WF);
        const int i   = rem / WF;
        const int j   = rem % WF;
        const float* xb = x + (size_t)b * CIN * HIN * WIN;

        float xv[NTAP];
#pragma unroll
        for (int ci = 0; ci < CIN; ci++) {
            const float* p = xb + (ci * HIN + i) * WIN + j;
            xv[ci * 4 + 0] = __ldg(p);
            xv[ci * 4 + 1] = __ldg(p + 1);
            xv[ci * 4 + 2] = __ldg(p + WIN);
            xv[ci * 4 + 3] = __ldg(p + WIN + 1);
        }
#pragma unroll
        for (int k = 0; k < NTAP; k++) {
            S[k] += xv[k];
#pragma unroll
            for (int l = 0; l <= k; l++)
                G[k * (k + 1) / 2 + l] = fmaf(xv[k], xv[l], G[k * (k + 1) / 2 + l]);
        }
    }

    // warp reduce all 90 accumulators
    const unsigned m = 0xffffffffu;
#pragma unroll
    for (int k = 0; k < NTAP; k++) {
        float a = S[k];
#pragma unroll
        for (int o = 16; o > 0; o >>= 1) a += __shfl_xor_sync(m, a, o);
        S[k] = a;
    }
#pragma unroll
    for (int k = 0; k < NTRI; k++) {
        float a = G[k];
#pragma unroll
        for (int o = 16; o > 0; o >>= 1) a += __shfl_xor_sync(m, a, o);
        G[k] = a;
    }

    __shared__ float red[8][NSTAT];
    const int warp = threadIdx.x >> 5, lane = threadIdx.x & 31;
    if (lane == 0) {
#pragma unroll
        for (int k = 0; k < NTAP; k++) red[warp][k] = S[k];
#pragma unroll
        for (int k = 0; k < NTRI; k++) red[warp][NTAP + k] = G[k];
    }
    __syncthreads();
    if (threadIdx.x < NSTAT) {
        float tot = 0.f;
#pragma unroll
        for (int w = 0; w < 8; w++) tot += red[w][threadIdx.x];
        atomicAdd(&g_stat[threadIdx.x], (double)tot);
    }
}

// ---------------------------------------------------------------------------
// Kernel 2: reconstruct per-channel conv stats from S/G, fold BN.
// mean_c = w_c.S/N ; E[conv^2]_c = w_c^T G w_c / N ; conv bias cancels in BN.
// ---------------------------------------------------------------------------
__global__ void finalize_kernel(const float* __restrict__ w,
                                const float* __restrict__ gamma,
                                const float* __restrict__ beta) {
    int c = threadIdx.x;
    if (c >= COUT) return;
    const double N = (double)NPIX;
    double wc[NTAP];
#pragma unroll
    for (int k = 0; k < NTAP; k++) wc[k] = (double)w[c * NTAP + k];

    double mean = 0.0;
#pragma unroll
    for (int k = 0; k < NTAP; k++) mean += wc[k] * g_stat[k];
    mean /= N;

    double e2 = 0.0;
#pragma unroll
    for (int k = 0; k < NTAP; k++) {
#pragma unroll
        for (int l = 0; l <= k; l++) {
            double g = g_stat[NTAP + k * (k + 1) / 2 + l];
            double t = wc[k] * wc[l] * g;
            e2 += (l == k) ? t : 2.0 * t;
        }
    }
    e2 /= N;
    double var = e2 - mean * mean;
    float scale = gamma[c] * rsqrtf((float)var + BN_EPS);
    g_scale[c] = scale;
    g_shift[c] = beta[c] - (float)mean * scale;
}

// ---------------------------------------------------------------------------
// Kernel 3: fused conv + BN + relu + tanh.approx + channel-sum + 2x2 mean.
// Block 256 threads -> 32x16 output tile; feat tile 33x17; x tile 3x18x34.
// Weights staged in smem (LDS.128), not constant (Blackwell LDC floor=8).
// ---------------------------------------------------------------------------
__global__ void __launch_bounds__(256) fused_out_kernel(const float* __restrict__ x,
                                                        const float* __restrict__ w,
                                                        float* __restrict__ out) {
    __shared__ __align__(16) float sx[CIN][18][36];
    __shared__ __align__(16) float st[17][34];
    __shared__ __align__(16) float sw[COUT * NTAP];
    __shared__ float ssc[COUT], ssh[COUT];

    const int tid = threadIdx.x;
    const int b   = blockIdx.z;
    const int oy0 = blockIdx.y * 16;
    const int ox0 = blockIdx.x * 32;

    if (tid < COUT * NTAP) sw[tid] = w[tid];
    if (tid < COUT) { ssc[tid] = g_scale[tid]; ssh[tid] = g_shift[tid]; }

    const float* xb = x + (size_t)b * CIN * HIN * WIN;
    for (int idx = tid; idx < CIN * 18 * 34; idx += 256) {
        const int col = idx % 34;
        const int t2  = idx / 34;
        const int r   = t2 % 18;
        const int ci  = t2 / 18;
        const int gr = oy0 + r, gc = ox0 + col;
        float v = 0.f;
        if (gr < HIN && gc < WIN) v = __ldg(&xb[(ci * HIN + gr) * WIN + gc]);
        sx[ci][r][col] = v;
    }
    __syncthreads();

    for (int p = tid; p < 33 * 17; p += 256) {
        const int fy = p / 33, fx = p % 33;
        float acc = 0.f;
        if (oy0 + fy < HF && ox0 + fx < WF) {
            float xv[NTAP];
#pragma unroll
            for (int ci = 0; ci < CIN; ci++) {
                xv[ci * 4 + 0] = sx[ci][fy][fx];
                xv[ci * 4 + 1] = sx[ci][fy][fx + 1];
                xv[ci * 4 + 2] = sx[ci][fy + 1][fx];
                xv[ci * 4 + 3] = sx[ci][fy + 1][fx + 1];
            }
#pragma unroll
            for (int c = 0; c < COUT; c++) {
                float v = 0.f;
#pragma unroll
                for (int k = 0; k < NTAP; k++) v = fmaf(sw[c * NTAP + k], xv[k], v);
                v = fmaf(v, ssc[c], ssh[c]);
                acc += tha(fmaxf(v, 0.f));
            }
        }
        st[fy][fx] = acc;
    }
    __syncthreads();

    const float inv = 1.0f / (COUT * KSZ * KSZ);
#pragma unroll
    for (int p = tid; p < 32 * 16; p += 256) {
        const int ty = p >> 5, tx = p & 31;
        const int oi = oy0 + ty, oj = ox0 + tx;
        if (oi < HO && oj < WO) {
            const float r = (st[ty][tx] + st[ty][tx + 1] +
                             st[ty + 1][tx] + st[ty + 1][tx + 1]) * inv;
            out[((size_t)b * HO + oi) * WO + oj] = r;
        }
    }
}

// ---------------------------------------------------------------------------
// kernel_launch: inputs: x, conv_w, conv_b (cancels under BN), gamma, beta
// ---------------------------------------------------------------------------
extern "C" void kernel_launch(void* const* d_in, const int* in_sizes, int n_in,
                              void* d_out, int out_size) {
    const float* x      = (const float*)d_in[0];
    const float* conv_w = (const float*)d_in[1];
    const float* gamma  = (const float*)d_in[3];
    const float* beta   = (const float*)d_in[4];
    float* out = (float*)d_out;

    prep_kernel<<<1, 128>>>();
    stats_kernel<<<592, 256>>>(x);
    finalize_kernel<<<1, COUT>>>(conv_w, gamma, beta);

    dim3 grid((WO + 31) / 32, (HO + 15) / 16, BATCH);   // 8 x 16 x 64
    fused_out_kernel<<<grid, 256>>>(x, conv_w, out);
}

// round 4
// speedup vs baseline: 3.4998x; 1.5639x over previous
#include <cuda_runtime.h>

#define KSZ   2
#define CIN   3
#define COUT  16
#define HIN   256
#define WIN   256
#define HF    255
#define WF    255
#define HO    254
#define WO    254
#define BATCH 64
#define NPIX  (BATCH * HF * WF)
#define BN_EPS 1e-5f

#define NTAP  12
#define NTRI  78
#define NSTAT (NTAP + NTRI)

// conv weights in constant memory: keeps them out of the register file
// (smem-staged weights made ptxas hoist 192 floats into regs -> occ collapse)
__constant__ float c_w[COUT * NTAP];

__device__ double g_stat[NSTAT];   // [0..11] tap sums S, [12..89] Gram lower-tri
__device__ float  g_scale[COUT];
__device__ float  g_shift[COUT];

__device__ __forceinline__ float tha(float x) {
    float y; asm("tanh.approx.f32 %0,%1;" : "=f"(y) : "f"(x)); return y;
}

// ---------------------------------------------------------------------------
// Kernel 0: zero statistics accumulators (graph replays reuse them)
// ---------------------------------------------------------------------------
__global__ void prep_kernel() {
    int t = threadIdx.x;
    if (t < NSTAT) g_stat[t] = 0.0;
}

// ---------------------------------------------------------------------------
// Kernel 1: channel-independent tap sums + Gram matrix (R3, validated).
// ---------------------------------------------------------------------------
__global__ void __launch_bounds__(256, 1) stats_kernel(const float* __restrict__ x) {
    float S[NTAP];
    float G[NTRI];
#pragma unroll
    for (int k = 0; k < NTAP; k++) S[k] = 0.f;
#pragma unroll
    for (int k = 0; k < NTRI; k++) G[k] = 0.f;

    const int stride = gridDim.x * blockDim.x;
    for (int idx = blockIdx.x * blockDim.x + threadIdx.x; idx < NPIX; idx += stride) {
        const int b   = idx / (HF * WF);
        const int rem = idx % (HF * WF);
        const int i   = rem / WF;
        const int j   = rem % WF;
        const float* xb = x + (size_t)b * CIN * HIN * WIN;

        float xv[NTAP];
#pragma unroll
        for (int ci = 0; ci < CIN; ci++) {
            const float* p = xb + (ci * HIN + i) * WIN + j;
            xv[ci * 4 + 0] = __ldg(p);
            xv[ci * 4 + 1] = __ldg(p + 1);
            xv[ci * 4 + 2] = __ldg(p + WIN);
            xv[ci * 4 + 3] = __ldg(p + WIN + 1);
        }
#pragma unroll
        for (int k = 0; k < NTAP; k++) {
            S[k] += xv[k];
#pragma unroll
            for (int l = 0; l <= k; l++)
                G[k * (k + 1) / 2 + l] = fmaf(xv[k], xv[l], G[k * (k + 1) / 2 + l]);
        }
    }

    const unsigned m = 0xffffffffu;
#pragma unroll
    for (int k = 0; k < NTAP; k++) {
        float a = S[k];
#pragma unroll
        for (int o = 16; o > 0; o >>= 1) a += __shfl_xor_sync(m, a, o);
        S[k] = a;
    }
#pragma unroll
    for (int k = 0; k < NTRI; k++) {
        float a = G[k];
#pragma unroll
        for (int o = 16; o > 0; o >>= 1) a += __shfl_xor_sync(m, a, o);
        G[k] = a;
    }

    __shared__ float red[8][NSTAT];
    const int warp = threadIdx.x >> 5, lane = threadIdx.x & 31;
    if (lane == 0) {
#pragma unroll
        for (int k = 0; k < NTAP; k++) red[warp][k] = S[k];
#pragma unroll
        for (int k = 0; k < NTRI; k++) red[warp][NTAP + k] = G[k];
    }
    __syncthreads();
    if (threadIdx.x < NSTAT) {
        float tot = 0.f;
#pragma unroll
        for (int w = 0; w < 8; w++) tot += red[w][threadIdx.x];
        atomicAdd(&g_stat[threadIdx.x], (double)tot);
    }
}

// ---------------------------------------------------------------------------
// Kernel 2: reconstruct per-channel stats from S/G, fold BN (bias cancels).
// ---------------------------------------------------------------------------
__global__ void finalize_kernel(const float* __restrict__ gamma,
                                const float* __restrict__ beta) {
    int c = threadIdx.x;
    if (c >= COUT) return;
    const double N = (double)NPIX;
    double wc[NTAP];
#pragma unroll
    for (int k = 0; k < NTAP; k++) wc[k] = (double)c_w[c * NTAP + k];

    double mean = 0.0;
#pragma unroll
    for (int k = 0; k < NTAP; k++) mean += wc[k] * g_stat[k];
    mean /= N;

    double e2 = 0.0;
#pragma unroll
    for (int k = 0; k < NTAP; k++) {
#pragma unroll
        for (int l = 0; l <= k; l++) {
            double g = g_stat[NTAP + k * (k + 1) / 2 + l];
            double t = wc[k] * wc[l] * g;
            e2 += (l == k) ? t : 2.0 * t;
        }
    }
    e2 /= N;
    double var = e2 - mean * mean;
    float scale = gamma[c] * rsqrtf((float)var + BN_EPS);
    g_scale[c] = scale;
    g_shift[c] = beta[c] - (float)mean * scale;
}

// ---------------------------------------------------------------------------
// Kernel 3: fused conv + BN + relu + tanh.approx + channel-sum + 2x2 mean.
// EXACT R1 structure (64 regs, occ 47.6%, issue 71.4%), tanhf -> tanh.approx.
// ---------------------------------------------------------------------------
__global__ void __launch_bounds__(256) fused_out_kernel(const float* __restrict__ x,
                                                        float* __restrict__ out) {
    __shared__ float sx[CIN][18][18];
    __shared__ float st[17][17];
    __shared__ float ssc[COUT], ssh[COUT];

    const int b   = blockIdx.z;
    const int oy0 = blockIdx.y * 16;
    const int ox0 = blockIdx.x * 16;
    const int tid = threadIdx.x;

    if (tid < COUT) { ssc[tid] = g_scale[tid]; ssh[tid] = g_shift[tid]; }

    const float* xb = x + (size_t)b * CIN * HIN * WIN;
    for (int idx = tid; idx < CIN * 18 * 18; idx += 256) {
        const int c   = idx / 324;
        const int rem = idx % 324;
        const int r   = rem / 18;
        const int col = rem % 18;
        const int gr = oy0 + r, gc = ox0 + col;
        float v = 0.f;
        if (gr < HIN && gc < WIN) v = __ldg(&xb[(c * HIN + gr) * WIN + gc]);
        sx[c][r][col] = v;
    }
    __syncthreads();

    for (int p = tid; p < 17 * 17; p += 256) {
        const int fy = p / 17, fx = p % 17;
        float acc = 0.f;
        if (oy0 + fy < HF && ox0 + fx < WF) {
            float xv[NTAP];
#pragma unroll
            for (int ci = 0; ci < CIN; ci++) {
                xv[ci * 4 + 0] = sx[ci][fy][fx];
                xv[ci * 4 + 1] = sx[ci][fy][fx + 1];
                xv[ci * 4 + 2] = sx[ci][fy + 1][fx];
                xv[ci * 4 + 3] = sx[ci][fy + 1][fx + 1];
            }
#pragma unroll
            for (int c = 0; c < COUT; c++) {
                float v = 0.f;
#pragma unroll
                for (int k = 0; k < NTAP; k++) v = fmaf(c_w[c * NTAP + k], xv[k], v);
                v = fmaf(v, ssc[c], ssh[c]);
                acc += tha(fmaxf(v, 0.f));
            }
        }
        st[fy][fx] = acc;
    }
    __syncthreads();

    const int ty = tid >> 4, tx = tid & 15;
    const int oi = oy0 + ty, oj = ox0 + tx;
    if (oi < HO && oj < WO) {
        const float r = (st[ty][tx] + st[ty][tx + 1] +
                         st[ty + 1][tx] + st[ty + 1][tx + 1]) *
                        (1.0f / (COUT * KSZ * KSZ));
        out[((size_t)b * HO + oi) * WO + oj] = r;
    }
}

// ---------------------------------------------------------------------------
// kernel_launch: inputs: x, conv_w, conv_b (cancels under BN), gamma, beta
// ---------------------------------------------------------------------------
extern "C" void kernel_launch(void* const* d_in, const int* in_sizes, int n_in,
                              void* d_out, int out_size) {
    const float* x      = (const float*)d_in[0];
    const float* conv_w = (const float*)d_in[1];
    const float* gamma  = (const float*)d_in[3];
    const float* beta   = (const float*)d_in[4];
    float* out = (float*)d_out;

    cudaMemcpyToSymbolAsync(c_w, conv_w, COUT * NTAP * sizeof(float),
                            0, cudaMemcpyDeviceToDevice, 0);

    prep_kernel<<<1, 128>>>();
    stats_kernel<<<592, 256>>>(x);
    finalize_kernel<<<1, COUT>>>(gamma, beta);

    dim3 grid((WO + 15) / 16, (HO + 15) / 16, BATCH);   // 16 x 16 x 64
    fused_out_kernel<<<grid, 256>>>(x, out);
}

// round 5
// speedup vs baseline: 3.7388x; 1.0683x over previous
#include <cuda_runtime.h>

#define KSZ   2
#define CIN   3
#define COUT  16
#define HIN   256
#define WIN   256
#define HF    255
#define WF    255
#define HO    254
#define WO    254
#define BATCH 64
#define NPIX  (BATCH * HF * WF)
#define BN_EPS 1e-5f

#define NTAP  12
#define NTRI  78
#define NSTAT (NTAP + NTRI)

typedef unsigned long long u64;

__device__ __forceinline__ u64 pk2(float lo, float hi) {
    u64 r; asm("mov.b64 %0,{%1,%2};" : "=l"(r) : "f"(lo), "f"(hi)); return r;
}
__device__ __forceinline__ void up2(u64 v, float& lo, float& hi) {
    asm("mov.b64 {%0,%1},%2;" : "=f"(lo), "=f"(hi) : "l"(v));
}
__device__ __forceinline__ u64 fma2(u64 a, u64 b, u64 c) {
    u64 d; asm("fma.rn.f32x2 %0,%1,%2,%3;" : "=l"(d) : "l"(a), "l"(b), "l"(c)); return d;
}
__device__ __forceinline__ u64 mul2(u64 a, u64 b) {
    u64 d; asm("mul.rn.f32x2 %0,%1,%2;" : "=l"(d) : "l"(a), "l"(b)); return d;
}
__device__ __forceinline__ float tha(float x) {
    float y; asm("tanh.approx.f32 %0,%1;" : "=f"(y) : "f"(x)); return y;
}

// ---------------- device scratch ----------------
__device__ double g_stat[NSTAT];      // tap sums + Gram lower-tri
__device__ u64    g_wp[COUT * NTAP];  // packed replicated weights
__device__ u64    g_scpk[COUT];       // packed BN scale
__device__ u64    g_shpk[COUT];       // packed BN shift

// ---------------------------------------------------------------------------
// Kernel 0: pack weights + zero stats
// ---------------------------------------------------------------------------
__global__ void prep_kernel(const float* __restrict__ w) {
    int t = threadIdx.x;
    if (t < COUT * NTAP) { float v = w[t]; g_wp[t] = pk2(v, v); }
    if (t < NSTAT) g_stat[t] = 0.0;
}

// ---------------------------------------------------------------------------
// Kernel 1: channel-independent tap sums + Gram matrix (validated R3).
// ---------------------------------------------------------------------------
__global__ void __launch_bounds__(256, 1) stats_kernel(const float* __restrict__ x) {
    float S[NTAP];
    float G[NTRI];
#pragma unroll
    for (int k = 0; k < NTAP; k++) S[k] = 0.f;
#pragma unroll
    for (int k = 0; k < NTRI; k++) G[k] = 0.f;

    const int stride = gridDim.x * blockDim.x;
    for (int idx = blockIdx.x * blockDim.x + threadIdx.x; idx < NPIX; idx += stride) {
        const int b   = idx / (HF * WF);
        const int rem = idx % (HF * WF);
        const int i   = rem / WF;
        const int j   = rem % WF;
        const float* xb = x + (size_t)b * CIN * HIN * WIN;

        float xv[NTAP];
#pragma unroll
        for (int ci = 0; ci < CIN; ci++) {
            const float* p = xb + (ci * HIN + i) * WIN + j;
            xv[ci * 4 + 0] = __ldg(p);
            xv[ci * 4 + 1] = __ldg(p + 1);
            xv[ci * 4 + 2] = __ldg(p + WIN);
            xv[ci * 4 + 3] = __ldg(p + WIN + 1);
        }
#pragma unroll
        for (int k = 0; k < NTAP; k++) {
            S[k] += xv[k];
#pragma unroll
            for (int l = 0; l <= k; l++)
                G[k * (k + 1) / 2 + l] = fmaf(xv[k], xv[l], G[k * (k + 1) / 2 + l]);
        }
    }

    const unsigned m = 0xffffffffu;
#pragma unroll
    for (int k = 0; k < NTAP; k++) {
        float a = S[k];
#pragma unroll
        for (int o = 16; o > 0; o >>= 1) a += __shfl_xor_sync(m, a, o);
        S[k] = a;
    }
#pragma unroll
    for (int k = 0; k < NTRI; k++) {
        float a = G[k];
#pragma unroll
        for (int o = 16; o > 0; o >>= 1) a += __shfl_xor_sync(m, a, o);
        G[k] = a;
    }

    __shared__ float red[8][NSTAT];
    const int warp = threadIdx.x >> 5, lane = threadIdx.x & 31;
    if (lane == 0) {
#pragma unroll
        for (int k = 0; k < NTAP; k++) red[warp][k] = S[k];
#pragma unroll
        for (int k = 0; k < NTRI; k++) red[warp][NTAP + k] = G[k];
    }
    __syncthreads();
    if (threadIdx.x < NSTAT) {
        float tot = 0.f;
#pragma unroll
        for (int w = 0; w < 8; w++) tot += red[w][threadIdx.x];
        atomicAdd(&g_stat[threadIdx.x], (double)tot);
    }
}

// ---------------------------------------------------------------------------
// Kernel 2: reconstruct per-channel stats, fold BN (conv bias cancels).
// ---------------------------------------------------------------------------
__global__ void finalize_kernel(const float* __restrict__ w,
                                const float* __restrict__ gamma,
                                const float* __restrict__ beta) {
    int c = threadIdx.x;
    if (c >= COUT) return;
    const double N = (double)NPIX;
    double wc[NTAP];
#pragma unroll
    for (int k = 0; k < NTAP; k++) wc[k] = (double)w[c * NTAP + k];

    double mean = 0.0;
#pragma unroll
    for (int k = 0; k < NTAP; k++) mean += wc[k] * g_stat[k];
    mean /= N;

    double e2 = 0.0;
#pragma unroll
    for (int k = 0; k < NTAP; k++) {
#pragma unroll
        for (int l = 0; l <= k; l++) {
            double g = g_stat[NTAP + k * (k + 1) / 2 + l];
            double t = wc[k] * wc[l] * g;
            e2 += (l == k) ? t : 2.0 * t;
        }
    }
    e2 /= N;
    double var = e2 - mean * mean;
    float scale = gamma[c] * rsqrtf((float)var + BN_EPS);
    float shift = beta[c] - (float)mean * scale;
    g_scpk[c] = pk2(scale, scale);
    g_shpk[c] = pk2(shift, shift);
}

// ---------------------------------------------------------------------------
// Kernel 3: fused conv+BN+relu+tanh+window, packed f32x2, smem weights.
// Block 256 thr = 32 pair-cols x 8 strips(4 rows). Feat tile 64x32,
// output tile 62x30. Taps in regs per strip; channel loop not unrolled so
// only 12 weight LDS.64 (broadcast) live at a time -> no reg hoisting.
// ---------------------------------------------------------------------------
__global__ void __launch_bounds__(256, 2) fused_out_kernel(const float* __restrict__ x,
                                                           float* __restrict__ out) {
    __shared__ u64 s_pe[CIN][33][33];   // packed x pairs: (x[2j], x[2j+1])
    __shared__ u64 s_st[32][33];        // packed per-pixel tanh sums
    __shared__ u64 s_sw[COUT * NTAP];
    __shared__ u64 s_sc[COUT], s_sh[COUT];

    const int tid = threadIdx.x;
    const int b   = blockIdx.z;
    const int oy0 = blockIdx.y * 30;
    const int ox0 = blockIdx.x * 62;

    for (int i = tid; i < COUT * NTAP; i += 256) s_sw[i] = g_wp[i];
    if (tid < COUT) { s_sc[tid] = g_scpk[tid]; s_sh[tid] = g_shpk[tid]; }

    // fill packed x tile (3 ci x 33 rows x 33 pair-cols; col 32 zero pad)
    const float* xb = x + (size_t)b * CIN * HIN * WIN;
    for (int idx = tid; idx < CIN * 33 * 33; idx += 256) {
        const int jc = idx % 33;
        const int t2 = idx / 33;
        const int r  = t2 % 33;
        const int ci = t2 / 33;
        const int gr = oy0 + r, gc = ox0 + 2 * jc;
        u64 v = 0ull;
        if (jc < 32 && gr < HIN && gc < WIN)
            v = *(const u64*)&xb[(size_t)(ci * HIN + gr) * WIN + gc];
        s_pe[ci][r][jc] = v;
    }
    __syncthreads();

    // per-thread strip: pair-col jp, feat rows r0..r0+3
    const int jp = tid & 31;
    const int wp = tid >> 5;
    const int r0 = wp * 4;

    u64 e[CIN][5], po[CIN][5];
#pragma unroll
    for (int ci = 0; ci < CIN; ci++) {
#pragma unroll
        for (int i = 0; i < 5; i++) {
            u64 ev = s_pe[ci][r0 + i][jp];
            float xr = *(const float*)&s_pe[ci][r0 + i][jp + 1];  // x[2jp+2]
            float lo, hi; up2(ev, lo, hi);
            e[ci][i]  = ev;
            po[ci][i] = pk2(hi, xr);                               // (x[2jp+1], x[2jp+2])
        }
    }

    float accA[4], accB[4];
#pragma unroll
    for (int i = 0; i < 4; i++) { accA[i] = 0.f; accB[i] = 0.f; }

#pragma unroll 1
    for (int c = 0; c < COUT; c++) {
        u64 w[NTAP];
#pragma unroll
        for (int k = 0; k < NTAP; k++) w[k] = s_sw[c * NTAP + k];
        const u64 sc = s_sc[c], sh = s_sh[c];
#pragma unroll
        for (int i = 0; i < 4; i++) {
            u64 v = mul2(w[0], e[0][i]);
            v = fma2(w[1],  po[0][i],     v);
            v = fma2(w[2],  e[0][i + 1],  v);
            v = fma2(w[3],  po[0][i + 1], v);
            v = fma2(w[4],  e[1][i],      v);
            v = fma2(w[5],  po[1][i],     v);
            v = fma2(w[6],  e[1][i + 1],  v);
            v = fma2(w[7],  po[1][i + 1], v);
            v = fma2(w[8],  e[2][i],      v);
            v = fma2(w[9],  po[2][i],     v);
            v = fma2(w[10], e[2][i + 1],  v);
            v = fma2(w[11], po[2][i + 1], v);
            v = fma2(v, sc, sh);                 // BN, packed
            float lo, hi; up2(v, lo, hi);
            accA[i] += tha(fmaxf(lo, 0.f));
            accB[i] += tha(fmaxf(hi, 0.f));
        }
    }
#pragma unroll
    for (int i = 0; i < 4; i++) s_st[r0 + i][jp] = pk2(accA[i], accB[i]);
    __syncthreads();

    // 2x2 window mean over the float view of s_st (row stride 66 floats)
    const float* stf = (const float*)s_st;
    const float inv = 1.0f / (COUT * KSZ * KSZ);
    for (int p = tid; p < 62 * 30; p += 256) {
        const int oy = p / 62, ox_ = p - oy * 62;
        const int oi = oy0 + oy, oj = ox0 + ox_;
        if (oi < HO && oj < WO) {
            const float* rp = stf + oy * 66 + ox_;
            out[(size_t)(b * HO + oi) * WO + oj] =
                (rp[0] + rp[1] + rp[66] + rp[67]) * inv;
        }
    }
}

// ---------------------------------------------------------------------------
// kernel_launch: inputs: x, conv_w, conv_b (cancels under BN), gamma, beta
// ---------------------------------------------------------------------------
extern "C" void kernel_launch(void* const* d_in, const int* in_sizes, int n_in,
                              void* d_out, int out_size) {
    const float* x      = (const float*)d_in[0];
    const float* conv_w = (const float*)d_in[1];
    const float* gamma  = (const float*)d_in[3];
    const float* beta   = (const float*)d_in[4];
    float* out = (float*)d_out;

    prep_kernel<<<1, 256>>>(conv_w);
    stats_kernel<<<592, 256>>>(x);
    finalize_kernel<<<1, COUT>>>(conv_w, gamma, beta);

    dim3 grid(5, 9, BATCH);   // 62-wide x 30-tall output tiles
    fused_out_kernel<<<grid, 256>>>(x, out);
}

// round 6
// speedup vs baseline: 3.9038x; 1.0441x over previous
#include <cuda_runtime.h>

#define KSZ   2
#define CIN   3
#define COUT  16
#define HIN   256
#define WIN   256
#define HF    255
#define WF    255
#define HO    254
#define WO    254
#define BATCH 64
#define NPIX  (BATCH * HF * WF)
#define BN_EPS 1e-5f

#define NTAP  12
#define NTRI  78
#define NSTAT (NTAP + NTRI)

typedef unsigned long long u64;

__device__ __forceinline__ u64 pk2(float lo, float hi) {
    u64 r; asm("mov.b64 %0,{%1,%2};" : "=l"(r) : "f"(lo), "f"(hi)); return r;
}
__device__ __forceinline__ void up2(u64 v, float& lo, float& hi) {
    asm("mov.b64 {%0,%1},%2;" : "=f"(lo), "=f"(hi) : "l"(v));
}
__device__ __forceinline__ u64 fma2(u64 a, u64 b, u64 c) {
    u64 d; asm("fma.rn.f32x2 %0,%1,%2,%3;" : "=l"(d) : "l"(a), "l"(b), "l"(c)); return d;
}
__device__ __forceinline__ u64 mul2(u64 a, u64 b) {
    u64 d; asm("mul.rn.f32x2 %0,%1,%2;" : "=l"(d) : "l"(a), "l"(b)); return d;
}
__device__ __forceinline__ float tha(float x) {
    float y; asm("tanh.approx.f32 %0,%1;" : "=f"(y) : "f"(x)); return y;
}

// ---------------- device scratch ----------------
__device__ double g_stat[NSTAT];
__device__ u64    g_wp[COUT * NTAP];
__device__ u64    g_scpk[COUT];
__device__ u64    g_shpk[COUT];

// ---------------------------------------------------------------------------
// Kernel 0: pack weights + zero stats
// ---------------------------------------------------------------------------
__global__ void prep_kernel(const float* __restrict__ w) {
    int t = threadIdx.x;
    if (t < COUT * NTAP) { float v = w[t]; g_wp[t] = pk2(v, v); }
    if (t < NSTAT) g_stat[t] = 0.0;
}

// ---------------------------------------------------------------------------
// Kernel 1: channel-independent tap sums + Gram matrix (validated).
// ---------------------------------------------------------------------------
__global__ void __launch_bounds__(256, 1) stats_kernel(const float* __restrict__ x) {
    float S[NTAP];
    float G[NTRI];
#pragma unroll
    for (int k = 0; k < NTAP; k++) S[k] = 0.f;
#pragma unroll
    for (int k = 0; k < NTRI; k++) G[k] = 0.f;

    const int stride = gridDim.x * blockDim.x;
    for (int idx = blockIdx.x * blockDim.x + threadIdx.x; idx < NPIX; idx += stride) {
        const int b   = idx / (HF * WF);
        const int rem = idx % (HF * WF);
        const int i   = rem / WF;
        const int j   = rem % WF;
        const float* xb = x + (size_t)b * CIN * HIN * WIN;

        float xv[NTAP];
#pragma unroll
        for (int ci = 0; ci < CIN; ci++) {
            const float* p = xb + (ci * HIN + i) * WIN + j;
            xv[ci * 4 + 0] = __ldg(p);
            xv[ci * 4 + 1] = __ldg(p + 1);
            xv[ci * 4 + 2] = __ldg(p + WIN);
            xv[ci * 4 + 3] = __ldg(p + WIN + 1);
        }
#pragma unroll
        for (int k = 0; k < NTAP; k++) {
            S[k] += xv[k];
#pragma unroll
            for (int l = 0; l <= k; l++)
                G[k * (k + 1) / 2 + l] = fmaf(xv[k], xv[l], G[k * (k + 1) / 2 + l]);
        }
    }

    const unsigned m = 0xffffffffu;
#pragma unroll
    for (int k = 0; k < NTAP; k++) {
        float a = S[k];
#pragma unroll
        for (int o = 16; o > 0; o >>= 1) a += __shfl_xor_sync(m, a, o);
        S[k] = a;
    }
#pragma unroll
    for (int k = 0; k < NTRI; k++) {
        float a = G[k];
#pragma unroll
        for (int o = 16; o > 0; o >>= 1) a += __shfl_xor_sync(m, a, o);
        G[k] = a;
    }

    __shared__ float red[8][NSTAT];
    const int warp = threadIdx.x >> 5, lane = threadIdx.x & 31;
    if (lane == 0) {
#pragma unroll
        for (int k = 0; k < NTAP; k++) red[warp][k] = S[k];
#pragma unroll
        for (int k = 0; k < NTRI; k++) red[warp][NTAP + k] = G[k];
    }
    __syncthreads();
    if (threadIdx.x < NSTAT) {
        float tot = 0.f;
#pragma unroll
        for (int w = 0; w < 8; w++) tot += red[w][threadIdx.x];
        atomicAdd(&g_stat[threadIdx.x], (double)tot);
    }
}

// ---------------------------------------------------------------------------
// Kernel 2: reconstruct per-channel stats, fold BN (conv bias cancels).
// ---------------------------------------------------------------------------
__global__ void finalize_kernel(const float* __restrict__ w,
                                const float* __restrict__ gamma,
                                const float* __restrict__ beta) {
    int c = threadIdx.x;
    if (c >= COUT) return;
    const double N = (double)NPIX;
    double wc[NTAP];
#pragma unroll
    for (int k = 0; k < NTAP; k++) wc[k] = (double)w[c * NTAP + k];

    double mean = 0.0;
#pragma unroll
    for (int k = 0; k < NTAP; k++) mean += wc[k] * g_stat[k];
    mean /= N;

    double e2 = 0.0;
#pragma unroll
    for (int k = 0; k < NTAP; k++) {
#pragma unroll
        for (int l = 0; l <= k; l++) {
            double g = g_stat[NTAP + k * (k + 1) / 2 + l];
            double t = wc[k] * wc[l] * g;
            e2 += (l == k) ? t : 2.0 * t;
        }
    }
    e2 /= N;
    double var = e2 - mean * mean;
    float scale = gamma[c] * rsqrtf((float)var + BN_EPS);
    float shift = beta[c] - (float)mean * scale;
    g_scpk[c] = pk2(scale, scale);
    g_shpk[c] = pk2(shift, shift);
}

// ---------------------------------------------------------------------------
// Kernel 3: fused conv+BN+relu+tanh+window. Packed f32x2.
// Block 256 thr = 32 pair-cols x 8 warps x 2-row strips -> feat 64x16,
// output 62x15. Even AND odd packed pairs precomputed in smem; 18 u64 taps
// in regs per strip; channel loop unroll 1, weights via 6x LDS.128.
// 3 CTAs/SM target (regs <= 83).
// ---------------------------------------------------------------------------
__global__ void __launch_bounds__(256, 3) fused_out_kernel(const float* __restrict__ x,
                                                           float* __restrict__ out) {
    __shared__ u64 s_pe[CIN][17][33];   // (x[2j], x[2j+1])
    __shared__ u64 s_po[CIN][17][32];   // (x[2j+1], x[2j+2])
    __shared__ u64 s_st[16][33];        // packed tanh sums
    __shared__ __align__(16) u64 s_sw[COUT * NTAP];
    __shared__ u64 s_sc[COUT], s_sh[COUT];

    const int tid = threadIdx.x;
    const int b   = blockIdx.z;
    const int oy0 = blockIdx.y * 15;
    const int ox0 = blockIdx.x * 62;

    for (int i = tid; i < COUT * NTAP; i += 256) s_sw[i] = g_wp[i];
    if (tid < COUT) { s_sc[tid] = g_scpk[tid]; s_sh[tid] = g_shpk[tid]; }

    // phase 1: even pairs from gmem (aligned LDG.64, coalesced)
    const float* xb = x + (size_t)b * CIN * HIN * WIN;
    for (int idx = tid; idx < CIN * 17 * 33; idx += 256) {
        const int jc = idx % 33;
        const int t2 = idx / 33;
        const int r  = t2 % 17;
        const int ci = t2 / 17;
        const int gr = oy0 + r, gc = ox0 + 2 * jc;
        u64 v = 0ull;
        if (gr < HIN && gc < WIN)
            v = *(const u64*)&xb[(size_t)(ci * HIN + gr) * WIN + gc];
        s_pe[ci][r][jc] = v;
    }
    __syncthreads();

    // phase 2: odd pairs from even pairs
    for (int idx = tid; idx < CIN * 17 * 32; idx += 256) {
        const int jc = idx & 31;
        const int t2 = idx >> 5;
        const int r  = t2 % 17;
        const int ci = t2 / 17;
        const float* pe = (const float*)&s_pe[ci][r][jc];
        s_po[ci][r][jc] = pk2(pe[1], pe[2]);
    }
    __syncthreads();

    // strip: pair-col jp, feat rows r0, r0+1
    const int jp = tid & 31;
    const int r0 = (tid >> 5) * 2;

    u64 e[CIN][3], o[CIN][3];
#pragma unroll
    for (int ci = 0; ci < CIN; ci++) {
#pragma unroll
        for (int i = 0; i < 3; i++) {
            e[ci][i] = s_pe[ci][r0 + i][jp];
            o[ci][i] = s_po[ci][r0 + i][jp];
        }
    }

    float accA[2], accB[2];
    accA[0] = accA[1] = accB[0] = accB[1] = 0.f;

#pragma unroll 1
    for (int c = 0; c < COUT; c++) {
        const ulonglong2* wv = (const ulonglong2*)&s_sw[c * NTAP];
        u64 w[NTAP];
#pragma unroll
        for (int k = 0; k < 6; k++) { ulonglong2 t = wv[k]; w[2 * k] = t.x; w[2 * k + 1] = t.y; }
        const u64 sc = s_sc[c], sh = s_sh[c];
#pragma unroll
        for (int i = 0; i < 2; i++) {
            u64 v = mul2(w[0], e[0][i]);
            v = fma2(w[1],  o[0][i],     v);
            v = fma2(w[2],  e[0][i + 1], v);
            v = fma2(w[3],  o[0][i + 1], v);
            v = fma2(w[4],  e[1][i],     v);
            v = fma2(w[5],  o[1][i],     v);
            v = fma2(w[6],  e[1][i + 1], v);
            v = fma2(w[7],  o[1][i + 1], v);
            v = fma2(w[8],  e[2][i],     v);
            v = fma2(w[9],  o[2][i],     v);
            v = fma2(w[10], e[2][i + 1], v);
            v = fma2(w[11], o[2][i + 1], v);
            v = fma2(v, sc, sh);
            float lo, hi; up2(v, lo, hi);
            accA[i] += tha(fmaxf(lo, 0.f));
            accB[i] += tha(fmaxf(hi, 0.f));
        }
    }
    s_st[r0 + 0][jp] = pk2(accA[0], accB[0]);
    s_st[r0 + 1][jp] = pk2(accA[1], accB[1]);
    __syncthreads();

    // 2x2 window mean (float view, row stride 66)
    const float* stf = (const float*)s_st;
    const float inv = 1.0f / (COUT * KSZ * KSZ);
    for (int p = tid; p < 62 * 15; p += 256) {
        const int oy = p / 62, ox_ = p - oy * 62;
        const int oi = oy0 + oy, oj = ox0 + ox_;
        if (oi < HO && oj < WO) {
            const float* rp = stf + oy * 66 + ox_;
            out[(size_t)(b * HO + oi) * WO + oj] =
                (rp[0] + rp[1] + rp[66] + rp[67]) * inv;
        }
    }
}

// ---------------------------------------------------------------------------
// kernel_launch: inputs: x, conv_w, conv_b (cancels under BN), gamma, beta
// ---------------------------------------------------------------------------
extern "C" void kernel_launch(void* const* d_in, const int* in_sizes, int n_in,
                              void* d_out, int out_size) {
    const float* x      = (const float*)d_in[0];
    const float* conv_w = (const float*)d_in[1];
    const float* gamma  = (const float*)d_in[3];
    const float* beta   = (const float*)d_in[4];
    float* out = (float*)d_out;

    prep_kernel<<<1, 256>>>(conv_w);
    stats_kernel<<<592, 256>>>(x);
    finalize_kernel<<<1, COUT>>>(conv_w, gamma, beta);

    dim3 grid(5, 17, BATCH);   // 62-wide x 15-tall output tiles
    fused_out_kernel<<<grid, 256>>>(x, out);
}

// round 7
// speedup vs baseline: 3.9109x; 1.0018x over previous
#include <cuda_runtime.h>

#define KSZ   2
#define CIN   3
#define COUT  16
#define HIN   256
#define WIN   256
#define HF    255
#define WF    255
#define HO    254
#define WO    254
#define BATCH 64
#define NPIX  (BATCH * HF * WF)
#define BN_EPS 1e-5f

#define NTAP  12
#define NTRI  78
#define NSTAT (NTAP + NTRI)

typedef unsigned long long u64;

__device__ __forceinline__ u64 pk2(float lo, float hi) {
    u64 r; asm("mov.b64 %0,{%1,%2};" : "=l"(r) : "f"(lo), "f"(hi)); return r;
}
__device__ __forceinline__ void up2(u64 v, float& lo, float& hi) {
    asm("mov.b64 {%0,%1},%2;" : "=f"(lo), "=f"(hi) : "l"(v));
}
__device__ __forceinline__ u64 fma2(u64 a, u64 b, u64 c) {
    u64 d; asm("fma.rn.f32x2 %0,%1,%2,%3;" : "=l"(d) : "l"(a), "l"(b), "l"(c)); return d;
}
__device__ __forceinline__ u64 mul2(u64 a, u64 b) {
    u64 d; asm("mul.rn.f32x2 %0,%1,%2;" : "=l"(d) : "l"(a), "l"(b)); return d;
}
__device__ __forceinline__ u64 add2(u64 a, u64 b) {
    u64 d; asm("add.rn.f32x2 %0,%1,%2;" : "=l"(d) : "l"(a), "l"(b)); return d;
}
__device__ __forceinline__ float tha(float x) {
    float y; asm("tanh.approx.f32 %0,%1;" : "=f"(y) : "f"(x)); return y;
}

// ---------------- device scratch ----------------
__device__ double g_stat[NSTAT];
__device__ u64    g_wp[COUT * NTAP];
__device__ u64    g_scpk[COUT];
__device__ u64    g_shpk[COUT];

// ---------------------------------------------------------------------------
// Kernel 0: pack weights + zero stats
// ---------------------------------------------------------------------------
__global__ void prep_kernel(const float* __restrict__ w) {
    int t = threadIdx.x;
    if (t < COUT * NTAP) { float v = w[t]; g_wp[t] = pk2(v, v); }
    if (t < NSTAT) g_stat[t] = 0.0;
}

// ---------------------------------------------------------------------------
// Kernel 1: channel-independent tap sums + Gram matrix (validated).
// ---------------------------------------------------------------------------
__global__ void __launch_bounds__(256, 1) stats_kernel(const float* __restrict__ x) {
    float S[NTAP];
    float G[NTRI];
#pragma unroll
    for (int k = 0; k < NTAP; k++) S[k] = 0.f;
#pragma unroll
    for (int k = 0; k < NTRI; k++) G[k] = 0.f;

    const int stride = gridDim.x * blockDim.x;
    for (int idx = blockIdx.x * blockDim.x + threadIdx.x; idx < NPIX; idx += stride) {
        const int b   = idx / (HF * WF);
        const int rem = idx % (HF * WF);
        const int i   = rem / WF;
        const int j   = rem % WF;
        const float* xb = x + (size_t)b * CIN * HIN * WIN;

        float xv[NTAP];
#pragma unroll
        for (int ci = 0; ci < CIN; ci++) {
            const float* p = xb + (ci * HIN + i) * WIN + j;
            xv[ci * 4 + 0] = __ldg(p);
            xv[ci * 4 + 1] = __ldg(p + 1);
            xv[ci * 4 + 2] = __ldg(p + WIN);
            xv[ci * 4 + 3] = __ldg(p + WIN + 1);
        }
#pragma unroll
        for (int k = 0; k < NTAP; k++) {
            S[k] += xv[k];
#pragma unroll
            for (int l = 0; l <= k; l++)
                G[k * (k + 1) / 2 + l] = fmaf(xv[k], xv[l], G[k * (k + 1) / 2 + l]);
        }
    }

    const unsigned m = 0xffffffffu;
#pragma unroll
    for (int k = 0; k < NTAP; k++) {
        float a = S[k];
#pragma unroll
        for (int o = 16; o > 0; o >>= 1) a += __shfl_xor_sync(m, a, o);
        S[k] = a;
    }
#pragma unroll
    for (int k = 0; k < NTRI; k++) {
        float a = G[k];
#pragma unroll
        for (int o = 16; o > 0; o >>= 1) a += __shfl_xor_sync(m, a, o);
        G[k] = a;
    }

    __shared__ float red[8][NSTAT];
    const int warp = threadIdx.x >> 5, lane = threadIdx.x & 31;
    if (lane == 0) {
#pragma unroll
        for (int k = 0; k < NTAP; k++) red[warp][k] = S[k];
#pragma unroll
        for (int k = 0; k < NTRI; k++) red[warp][NTAP + k] = G[k];
    }
    __syncthreads();
    if (threadIdx.x < NSTAT) {
        float tot = 0.f;
#pragma unroll
        for (int w = 0; w < 8; w++) tot += red[w][threadIdx.x];
        atomicAdd(&g_stat[threadIdx.x], (double)tot);
    }
}

// ---------------------------------------------------------------------------
// Kernel 2: reconstruct per-channel stats, fold BN (conv bias cancels).
// ---------------------------------------------------------------------------
__global__ void finalize_kernel(const float* __restrict__ w,
                                const float* __restrict__ gamma,
                                const float* __restrict__ beta) {
    int c = threadIdx.x;
    if (c >= COUT) return;
    const double N = (double)NPIX;
    double wc[NTAP];
#pragma unroll
    for (int k = 0; k < NTAP; k++) wc[k] = (double)w[c * NTAP + k];

    double mean = 0.0;
#pragma unroll
    for (int k = 0; k < NTAP; k++) mean += wc[k] * g_stat[k];
    mean /= N;

    double e2 = 0.0;
#pragma unroll
    for (int k = 0; k < NTAP; k++) {
#pragma unroll
        for (int l = 0; l <= k; l++) {
            double g = g_stat[NTAP + k * (k + 1) / 2 + l];
            double t = wc[k] * wc[l] * g;
            e2 += (l == k) ? t : 2.0 * t;
        }
    }
    e2 /= N;
    double var = e2 - mean * mean;
    float scale = gamma[c] * rsqrtf((float)var + BN_EPS);
    float shift = beta[c] - (float)mean * scale;
    g_scpk[c] = pk2(scale, scale);
    g_shpk[c] = pk2(shift, shift);
}

// ---------------------------------------------------------------------------
// Kernel 3: fused conv+BN+relu+tanh+window. Packed f32x2.
// R6 structure; conv accumulation split into two independent 6-op
// half-chains per pixel-pair (4 chains in flight per channel iteration)
// to cut the FFMA2 dependency stall.
// ---------------------------------------------------------------------------
__global__ void __launch_bounds__(256, 3) fused_out_kernel(const float* __restrict__ x,
                                                           float* __restrict__ out) {
    __shared__ u64 s_pe[CIN][17][33];   // (x[2j], x[2j+1])
    __shared__ u64 s_po[CIN][17][32];   // (x[2j+1], x[2j+2])
    __shared__ u64 s_st[16][33];        // packed tanh sums
    __shared__ __align__(16) u64 s_sw[COUT * NTAP];
    __shared__ u64 s_sc[COUT], s_sh[COUT];

    const int tid = threadIdx.x;
    const int b   = blockIdx.z;
    const int oy0 = blockIdx.y * 15;
    const int ox0 = blockIdx.x * 62;

    for (int i = tid; i < COUT * NTAP; i += 256) s_sw[i] = g_wp[i];
    if (tid < COUT) { s_sc[tid] = g_scpk[tid]; s_sh[tid] = g_shpk[tid]; }

    // phase 1: even pairs from gmem (aligned LDG.64, coalesced)
    const float* xb = x + (size_t)b * CIN * HIN * WIN;
    for (int idx = tid; idx < CIN * 17 * 33; idx += 256) {
        const int jc = idx % 33;
        const int t2 = idx / 33;
        const int r  = t2 % 17;
        const int ci = t2 / 17;
        const int gr = oy0 + r, gc = ox0 + 2 * jc;
        u64 v = 0ull;
        if (gr < HIN && gc < WIN)
            v = *(const u64*)&xb[(size_t)(ci * HIN + gr) * WIN + gc];
        s_pe[ci][r][jc] = v;
    }
    __syncthreads();

    // phase 2: odd pairs from even pairs
    for (int idx = tid; idx < CIN * 17 * 32; idx += 256) {
        const int jc = idx & 31;
        const int t2 = idx >> 5;
        const int r  = t2 % 17;
        const int ci = t2 / 17;
        const float* pe = (const float*)&s_pe[ci][r][jc];
        s_po[ci][r][jc] = pk2(pe[1], pe[2]);
    }
    __syncthreads();

    // strip: pair-col jp, feat rows r0, r0+1
    const int jp = tid & 31;
    const int r0 = (tid >> 5) * 2;

    u64 e[CIN][3], o[CIN][3];
#pragma unroll
    for (int ci = 0; ci < CIN; ci++) {
#pragma unroll
        for (int i = 0; i < 3; i++) {
            e[ci][i] = s_pe[ci][r0 + i][jp];
            o[ci][i] = s_po[ci][r0 + i][jp];
        }
    }

    float accA[2], accB[2];
    accA[0] = accA[1] = accB[0] = accB[1] = 0.f;

#pragma unroll 1
    for (int c = 0; c < COUT; c++) {
        const ulonglong2* wv = (const ulonglong2*)&s_sw[c * NTAP];
        u64 w[NTAP];
#pragma unroll
        for (int k = 0; k < 6; k++) { ulonglong2 t = wv[k]; w[2 * k] = t.x; w[2 * k + 1] = t.y; }
        const u64 sc = s_sc[c], sh = s_sh[c];
#pragma unroll
        for (int i = 0; i < 2; i++) {
            // two independent 6-op half-chains per pixel pair
            u64 v0 = mul2(w[0], e[0][i]);
            v0 = fma2(w[1],  o[0][i],     v0);
            v0 = fma2(w[2],  e[0][i + 1], v0);
            v0 = fma2(w[3],  o[0][i + 1], v0);
            v0 = fma2(w[4],  e[1][i],     v0);
            v0 = fma2(w[5],  o[1][i],     v0);
            u64 v1 = mul2(w[6], e[1][i + 1]);
            v1 = fma2(w[7],  o[1][i + 1], v1);
            v1 = fma2(w[8],  e[2][i],     v1);
            v1 = fma2(w[9],  o[2][i],     v1);
            v1 = fma2(w[10], e[2][i + 1], v1);
            v1 = fma2(w[11], o[2][i + 1], v1);
            u64 v = add2(v0, v1);
            v = fma2(v, sc, sh);
            float lo, hi; up2(v, lo, hi);
            accA[i] += tha(fmaxf(lo, 0.f));
            accB[i] += tha(fmaxf(hi, 0.f));
        }
    }
    s_st[r0 + 0][jp] = pk2(accA[0], accB[0]);
    s_st[r0 + 1][jp] = pk2(accA[1], accB[1]);
    __syncthreads();

    // 2x2 window mean (float view, row stride 66)
    const float* stf = (const float*)s_st;
    const float inv = 1.0f / (COUT * KSZ * KSZ);
    for (int p = tid; p < 62 * 15; p += 256) {
        const int oy = p / 62, ox_ = p - oy * 62;
        const int oi = oy0 + oy, oj = ox0 + ox_;
        if (oi < HO && oj < WO) {
            const float* rp = stf + oy * 66 + ox_;
            out[(size_t)(b * HO + oi) * WO + oj] =
                (rp[0] + rp[1] + rp[66] + rp[67]) * inv;
        }
    }
}

// ---------------------------------------------------------------------------
// kernel_launch: inputs: x, conv_w, conv_b (cancels under BN), gamma, beta
// ---------------------------------------------------------------------------
extern "C" void kernel_launch(void* const* d_in, const int* in_sizes, int n_in,
                              void* d_out, int out_size) {
    const float* x      = (const float*)d_in[0];
    const float* conv_w = (const float*)d_in[1];
    const float* gamma  = (const float*)d_in[3];
    const float* beta   = (const float*)d_in[4];
    float* out = (float*)d_out;

    prep_kernel<<<1, 256>>>(conv_w);
    stats_kernel<<<592, 256>>>(x);
    finalize_kernel<<<1, COUT>>>(conv_w, gamma, beta);

    dim3 grid(5, 17, BATCH);   // 62-wide x 15-tall output tiles
    fused_out_kernel<<<grid, 256>>>(x, out);
}

// round 8
// speedup vs baseline: 4.2869x; 1.0961x over previous
#include <cuda_runtime.h>

#define KSZ   2
#define CIN   3
#define COUT  16
#define HIN   256
#define WIN   256
#define HF    255
#define WF    255
#define HO    254
#define WO    254
#define BATCH 64
#define NPIX  (BATCH * HF * WF)
#define BN_EPS 1e-5f

#define NTAP  12
#define NTRI  78
#define NSTAT (NTAP + NTRI)

typedef unsigned long long u64;

__device__ __forceinline__ u64 pk2(float lo, float hi) {
    u64 r; asm("mov.b64 %0,{%1,%2};" : "=l"(r) : "f"(lo), "f"(hi)); return r;
}
__device__ __forceinline__ void up2(u64 v, float& lo, float& hi) {
    asm("mov.b64 {%0,%1},%2;" : "=f"(lo), "=f"(hi) : "l"(v));
}
__device__ __forceinline__ u64 fma2(u64 a, u64 b, u64 c) {
    u64 d; asm("fma.rn.f32x2 %0,%1,%2,%3;" : "=l"(d) : "l"(a), "l"(b), "l"(c)); return d;
}
__device__ __forceinline__ u64 mul2(u64 a, u64 b) {
    u64 d; asm("mul.rn.f32x2 %0,%1,%2;" : "=l"(d) : "l"(a), "l"(b)); return d;
}
__device__ __forceinline__ u64 add2(u64 a, u64 b) {
    u64 d; asm("add.rn.f32x2 %0,%1,%2;" : "=l"(d) : "l"(a), "l"(b)); return d;
}
__device__ __forceinline__ float tha(float x) {
    float y; asm("tanh.approx.f32 %0,%1;" : "=f"(y) : "f"(x)); return y;
}

// ---------------- constant memory: uniform-port operand streams ----------------
__constant__ u64 c_wp[COUT * NTAP];   // packed replicated weights
__constant__ u64 c_post[2 * COUT];    // [0..15] packed scale, [16..31] packed shift

// ---------------- device scratch ----------------
__device__ double g_stat[NSTAT];
__device__ u64    g_wp[COUT * NTAP];
__device__ u64    g_post[2 * COUT];

// ---------------------------------------------------------------------------
// Kernel 0: pack weights + zero stats
// ---------------------------------------------------------------------------
__global__ void prep_kernel(const float* __restrict__ w) {
    int t = threadIdx.x;
    if (t < COUT * NTAP) { float v = w[t]; g_wp[t] = pk2(v, v); }
    if (t < NSTAT) g_stat[t] = 0.0;
}

// ---------------------------------------------------------------------------
// Kernel 1: channel-independent tap sums + Gram matrix (validated).
// ---------------------------------------------------------------------------
__global__ void __launch_bounds__(256, 1) stats_kernel(const float* __restrict__ x) {
    float S[NTAP];
    float G[NTRI];
#pragma unroll
    for (int k = 0; k < NTAP; k++) S[k] = 0.f;
#pragma unroll
    for (int k = 0; k < NTRI; k++) G[k] = 0.f;

    const int stride = gridDim.x * blockDim.x;
    for (int idx = blockIdx.x * blockDim.x + threadIdx.x; idx < NPIX; idx += stride) {
        const int b   = idx / (HF * WF);
        const int rem = idx % (HF * WF);
        const int i   = rem / WF;
        const int j   = rem % WF;
        const float* xb = x + (size_t)b * CIN * HIN * WIN;

        float xv[NTAP];
#pragma unroll
        for (int ci = 0; ci < CIN; ci++) {
            const float* p = xb + (ci * HIN + i) * WIN + j;
            xv[ci * 4 + 0] = __ldg(p);
            xv[ci * 4 + 1] = __ldg(p + 1);
            xv[ci * 4 + 2] = __ldg(p + WIN);
            xv[ci * 4 + 3] = __ldg(p + WIN + 1);
        }
#pragma unroll
        for (int k = 0; k < NTAP; k++) {
            S[k] += xv[k];
#pragma unroll
            for (int l = 0; l <= k; l++)
                G[k * (k + 1) / 2 + l] = fmaf(xv[k], xv[l], G[k * (k + 1) / 2 + l]);
        }
    }

    const unsigned m = 0xffffffffu;
#pragma unroll
    for (int k = 0; k < NTAP; k++) {
        float a = S[k];
#pragma unroll
        for (int o = 16; o > 0; o >>= 1) a += __shfl_xor_sync(m, a, o);
        S[k] = a;
    }
#pragma unroll
    for (int k = 0; k < NTRI; k++) {
        float a = G[k];
#pragma unroll
        for (int o = 16; o > 0; o >>= 1) a += __shfl_xor_sync(m, a, o);
        G[k] = a;
    }

    __shared__ float red[8][NSTAT];
    const int warp = threadIdx.x >> 5, lane = threadIdx.x & 31;
    if (lane == 0) {
#pragma unroll
        for (int k = 0; k < NTAP; k++) red[warp][k] = S[k];
#pragma unroll
        for (int k = 0; k < NTRI; k++) red[warp][NTAP + k] = G[k];
    }
    __syncthreads();
    if (threadIdx.x < NSTAT) {
        float tot = 0.f;
#pragma unroll
        for (int w = 0; w < 8; w++) tot += red[w][threadIdx.x];
        atomicAdd(&g_stat[threadIdx.x], (double)tot);
    }
}

// ---------------------------------------------------------------------------
// Kernel 2: reconstruct per-channel stats, fold BN (conv bias cancels).
// ---------------------------------------------------------------------------
__global__ void finalize_kernel(const float* __restrict__ w,
                                const float* __restrict__ gamma,
                                const float* __restrict__ beta) {
    int c = threadIdx.x;
    if (c >= COUT) return;
    const double N = (double)NPIX;
    double wc[NTAP];
#pragma unroll
    for (int k = 0; k < NTAP; k++) wc[k] = (double)w[c * NTAP + k];

    double mean = 0.0;
#pragma unroll
    for (int k = 0; k < NTAP; k++) mean += wc[k] * g_stat[k];
    mean /= N;

    double e2 = 0.0;
#pragma unroll
    for (int k = 0; k < NTAP; k++) {
#pragma unroll
        for (int l = 0; l <= k; l++) {
            double g = g_stat[NTAP + k * (k + 1) / 2 + l];
            double t = wc[k] * wc[l] * g;
            e2 += (l == k) ? t : 2.0 * t;
        }
    }
    e2 /= N;
    double var = e2 - mean * mean;
    float scale = gamma[c] * rsqrtf((float)var + BN_EPS);
    float shift = beta[c] - (float)mean * scale;
    g_post[c]        = pk2(scale, scale);
    g_post[COUT + c] = pk2(shift, shift);
}

// ---------------------------------------------------------------------------
// Kernel 3: fused conv+BN+relu+tanh+window. Packed f32x2.
// Weights + BN scale/shift come from __constant__ via the uniform port
// (LDCU -> UR, floor 1, separate from LSU); taps in regs; 2-row strips.
// Target 4 CTAs/SM (regs <= 64).
// ---------------------------------------------------------------------------
__global__ void __launch_bounds__(256, 4) fused_out_kernel(const float* __restrict__ x,
                                                           float* __restrict__ out) {
    __shared__ u64 s_pe[CIN][17][33];   // (x[2j], x[2j+1])
    __shared__ u64 s_po[CIN][17][32];   // (x[2j+1], x[2j+2])
    __shared__ u64 s_st[16][33];        // packed tanh sums

    const int tid = threadIdx.x;
    const int b   = blockIdx.z;
    const int oy0 = blockIdx.y * 15;
    const int ox0 = blockIdx.x * 62;

    // phase 1: even pairs from gmem (aligned LDG.64, coalesced)
    const float* xb = x + (size_t)b * CIN * HIN * WIN;
    for (int idx = tid; idx < CIN * 17 * 33; idx += 256) {
        const int jc = idx % 33;
        const int t2 = idx / 33;
        const int r  = t2 % 17;
        const int ci = t2 / 17;
        const int gr = oy0 + r, gc = ox0 + 2 * jc;
        u64 v = 0ull;
        if (gr < HIN && gc < WIN)
            v = *(const u64*)&xb[(size_t)(ci * HIN + gr) * WIN + gc];
        s_pe[ci][r][jc] = v;
    }
    __syncthreads();

    // phase 2: odd pairs from even pairs
    for (int idx = tid; idx < CIN * 17 * 32; idx += 256) {
        const int jc = idx & 31;
        const int t2 = idx >> 5;
        const int r  = t2 % 17;
        const int ci = t2 / 17;
        const float* pe = (const float*)&s_pe[ci][r][jc];
        s_po[ci][r][jc] = pk2(pe[1], pe[2]);
    }
    __syncthreads();

    // strip: pair-col jp, feat rows r0, r0+1
    const int jp = tid & 31;
    const int r0 = (tid >> 5) * 2;

    u64 e[CIN][3], o[CIN][3];
#pragma unroll
    for (int ci = 0; ci < CIN; ci++) {
#pragma unroll
        for (int i = 0; i < 3; i++) {
            e[ci][i] = s_pe[ci][r0 + i][jp];
            o[ci][i] = s_po[ci][r0 + i][jp];
        }
    }

    float accA[2], accB[2];
    accA[0] = accA[1] = accB[0] = accB[1] = 0.f;

#pragma unroll 1
    for (int c = 0; c < COUT; c++) {
        const u64* w = &c_wp[c * NTAP];       // warp-uniform -> LDCU/UR
        const u64 sc = c_post[c];
        const u64 sh = c_post[COUT + c];
#pragma unroll
        for (int i = 0; i < 2; i++) {
            u64 v0 = mul2(w[0], e[0][i]);
            v0 = fma2(w[1],  o[0][i],     v0);
            v0 = fma2(w[2],  e[0][i + 1], v0);
            v0 = fma2(w[3],  o[0][i + 1], v0);
            v0 = fma2(w[4],  e[1][i],     v0);
            v0 = fma2(w[5],  o[1][i],     v0);
            u64 v1 = mul2(w[6], e[1][i + 1]);
            v1 = fma2(w[7],  o[1][i + 1], v1);
            v1 = fma2(w[8],  e[2][i],     v1);
            v1 = fma2(w[9],  o[2][i],     v1);
            v1 = fma2(w[10], e[2][i + 1], v1);
            v1 = fma2(w[11], o[2][i + 1], v1);
            u64 v = add2(v0, v1);
            v = fma2(v, sc, sh);
            float lo, hi; up2(v, lo, hi);
            accA[i] += tha(fmaxf(lo, 0.f));
            accB[i] += tha(fmaxf(hi, 0.f));
        }
    }
    s_st[r0 + 0][jp] = pk2(accA[0], accB[0]);
    s_st[r0 + 1][jp] = pk2(accA[1], accB[1]);
    __syncthreads();

    // 2x2 window mean (float view, row stride 66)
    const float* stf = (const float*)s_st;
    const float inv = 1.0f / (COUT * KSZ * KSZ);
    for (int p = tid; p < 62 * 15; p += 256) {
        const int oy = p / 62, ox_ = p - oy * 62;
        const int oi = oy0 + oy, oj = ox0 + ox_;
        if (oi < HO && oj < WO) {
            const float* rp = stf + oy * 66 + ox_;
            out[(size_t)(b * HO + oi) * WO + oj] =
                (rp[0] + rp[1] + rp[66] + rp[67]) * inv;
        }
    }
}

// ---------------------------------------------------------------------------
// kernel_launch: inputs: x, conv_w, conv_b (cancels under BN), gamma, beta
// ---------------------------------------------------------------------------
extern "C" void kernel_launch(void* const* d_in, const int* in_sizes, int n_in,
                              void* d_out, int out_size) {
    const float* x      = (const float*)d_in[0];
    const float* conv_w = (const float*)d_in[1];
    const float* gamma  = (const float*)d_in[3];
    const float* beta   = (const float*)d_in[4];
    float* out = (float*)d_out;

    void* p_wp = 0;  void* p_post = 0;
    cudaGetSymbolAddress(&p_wp, g_wp);
    cudaGetSymbolAddress(&p_post, g_post);

    prep_kernel<<<1, 256>>>(conv_w);
    cudaMemcpyToSymbolAsync(c_wp, p_wp, COUT * NTAP * sizeof(u64),
                            0, cudaMemcpyDeviceToDevice, 0);

    stats_kernel<<<592, 256>>>(x);
    finalize_kernel<<<1, COUT>>>(conv_w, gamma, beta);
    cudaMemcpyToSymbolAsync(c_post, p_post, 2 * COUT * sizeof(u64),
                            0, cudaMemcpyDeviceToDevice, 0);

    dim3 grid(5, 17, BATCH);   // 62-wide x 15-tall output tiles
    fused_out_kernel<<<grid, 256>>>(x, out);
}

// round 9
// speedup vs baseline: 4.3714x; 1.0197x over previous
#include <cuda_runtime.h>

#define KSZ   2
#define CIN   3
#define COUT  16
#define HIN   256
#define WIN   256
#define HF    255
#define WF    255
#define HO    254
#define WO    254
#define BATCH 64
#define NPIX  (BATCH * HF * WF)
#define BN_EPS 1e-5f

#define NTAP  12
#define NTRI  78
#define NSTAT (NTAP + NTRI)
#define CSTR  13            // per-channel constant stride: 12 scaled weights + shift

typedef unsigned long long u64;

__device__ __forceinline__ u64 pk2(float lo, float hi) {
    u64 r; asm("mov.b64 %0,{%1,%2};" : "=l"(r) : "f"(lo), "f"(hi)); return r;
}
__device__ __forceinline__ void up2(u64 v, float& lo, float& hi) {
    asm("mov.b64 {%0,%1},%2;" : "=f"(lo), "=f"(hi) : "l"(v));
}
__device__ __forceinline__ u64 fma2(u64 a, u64 b, u64 c) {
    u64 d; asm("fma.rn.f32x2 %0,%1,%2,%3;" : "=l"(d) : "l"(a), "l"(b), "l"(c)); return d;
}
__device__ __forceinline__ u64 mul2(u64 a, u64 b) {
    u64 d; asm("mul.rn.f32x2 %0,%1,%2;" : "=l"(d) : "l"(a), "l"(b)); return d;
}
__device__ __forceinline__ u64 add2(u64 a, u64 b) {
    u64 d; asm("add.rn.f32x2 %0,%1,%2;" : "=l"(d) : "l"(a), "l"(b)); return d;
}
__device__ __forceinline__ float tha(float x) {
    float y; asm("tanh.approx.f32 %0,%1;" : "=f"(y) : "f"(x)); return y;
}

// ---------------- constant: per-channel [12 x packed w*scale, packed shift] ----------------
__constant__ u64 c_all[COUT * CSTR];

// ---------------- device scratch ----------------
__device__ double g_stat[NSTAT];
__device__ u64    g_all[COUT * CSTR];

// ---------------------------------------------------------------------------
// Kernel 0: zero statistics accumulators
// ---------------------------------------------------------------------------
__global__ void prep_kernel() {
    int t = threadIdx.x;
    if (t < NSTAT) g_stat[t] = 0.0;
}

// ---------------------------------------------------------------------------
// Kernel 1: channel-independent tap sums + Gram matrix (validated).
// ---------------------------------------------------------------------------
__global__ void __launch_bounds__(256, 1) stats_kernel(const float* __restrict__ x) {
    float S[NTAP];
    float G[NTRI];
#pragma unroll
    for (int k = 0; k < NTAP; k++) S[k] = 0.f;
#pragma unroll
    for (int k = 0; k < NTRI; k++) G[k] = 0.f;

    const int stride = gridDim.x * blockDim.x;
    for (int idx = blockIdx.x * blockDim.x + threadIdx.x; idx < NPIX; idx += stride) {
        const int b   = idx / (HF * WF);
        const int rem = idx % (HF * WF);
        const int i   = rem / WF;
        const int j   = rem % WF;
        const float* xb = x + (size_t)b * CIN * HIN * WIN;

        float xv[NTAP];
#pragma unroll
        for (int ci = 0; ci < CIN; ci++) {
            const float* p = xb + (ci * HIN + i) * WIN + j;
            xv[ci * 4 + 0] = __ldg(p);
            xv[ci * 4 + 1] = __ldg(p + 1);
            xv[ci * 4 + 2] = __ldg(p + WIN);
            xv[ci * 4 + 3] = __ldg(p + WIN + 1);
        }
#pragma unroll
        for (int k = 0; k < NTAP; k++) {
            S[k] += xv[k];
#pragma unroll
            for (int l = 0; l <= k; l++)
                G[k * (k + 1) / 2 + l] = fmaf(xv[k], xv[l], G[k * (k + 1) / 2 + l]);
        }
    }

    const unsigned m = 0xffffffffu;
#pragma unroll
    for (int k = 0; k < NTAP; k++) {
        float a = S[k];
#pragma unroll
        for (int o = 16; o > 0; o >>= 1) a += __shfl_xor_sync(m, a, o);
        S[k] = a;
    }
#pragma unroll
    for (int k = 0; k < NTRI; k++) {
        float a = G[k];
#pragma unroll
        for (int o = 16; o > 0; o >>= 1) a += __shfl_xor_sync(m, a, o);
        G[k] = a;
    }

    __shared__ float red[8][NSTAT];
    const int warp = threadIdx.x >> 5, lane = threadIdx.x & 31;
    if (lane == 0) {
#pragma unroll
        for (int k = 0; k < NTAP; k++) red[warp][k] = S[k];
#pragma unroll
        for (int k = 0; k < NTRI; k++) red[warp][NTAP + k] = G[k];
    }
    __syncthreads();
    if (threadIdx.x < NSTAT) {
        float tot = 0.f;
#pragma unroll
        for (int w = 0; w < 8; w++) tot += red[w][threadIdx.x];
        atomicAdd(&g_stat[threadIdx.x], (double)tot);
    }
}

// ---------------------------------------------------------------------------
// Kernel 2: reconstruct per-channel stats, fold BN, pack scaled weights +
// shift per channel (conv bias cancels under train-mode BN).
// ---------------------------------------------------------------------------
__global__ void finalize_kernel(const float* __restrict__ w,
                                const float* __restrict__ gamma,
                                const float* __restrict__ beta) {
    int c = threadIdx.x;
    if (c >= COUT) return;
    const double N = (double)NPIX;
    double wc[NTAP];
#pragma unroll
    for (int k = 0; k < NTAP; k++) wc[k] = (double)w[c * NTAP + k];

    double mean = 0.0;
#pragma unroll
    for (int k = 0; k < NTAP; k++) mean += wc[k] * g_stat[k];
    mean /= N;

    double e2 = 0.0;
#pragma unroll
    for (int k = 0; k < NTAP; k++) {
#pragma unroll
        for (int l = 0; l <= k; l++) {
            double g = g_stat[NTAP + k * (k + 1) / 2 + l];
            double t = wc[k] * wc[l] * g;
            e2 += (l == k) ? t : 2.0 * t;
        }
    }
    e2 /= N;
    double var = e2 - mean * mean;
    float scale = gamma[c] * rsqrtf((float)var + BN_EPS);
    float shift = beta[c] - (float)mean * scale;
#pragma unroll
    for (int k = 0; k < NTAP; k++) {
        float ws = w[c * NTAP + k] * scale;
        g_all[c * CSTR + k] = pk2(ws, ws);
    }
    g_all[c * CSTR + NTAP] = pk2(shift, shift);
}

// ---------------------------------------------------------------------------
// Kernel 3: fused conv+BN+relu+tanh+window. Packed f32x2.
// Scaled weights + shift via uniform port (LDCU); shift folded into chain 0
// init; odd pairs built in registers (no phase-2 smem pass).
// ---------------------------------------------------------------------------
__global__ void __launch_bounds__(256, 4) fused_out_kernel(const float* __restrict__ x,
                                                           float* __restrict__ out) {
    __shared__ u64 s_pe[CIN][17][33];   // (x[2j], x[2j+1]) pairs, col 32 = next pair
    __shared__ u64 s_st[16][33];        // packed tanh sums

    const int tid = threadIdx.x;
    const int b   = blockIdx.z;
    const int oy0 = blockIdx.y * 15;
    const int ox0 = blockIdx.x * 62;

    // even pairs from gmem (aligned LDG.64, coalesced)
    const float* xb = x + (size_t)b * CIN * HIN * WIN;
    for (int idx = tid; idx < CIN * 17 * 33; idx += 256) {
        const int jc = idx % 33;
        const int t2 = idx / 33;
        const int r  = t2 % 17;
        const int ci = t2 / 17;
        const int gr = oy0 + r, gc = ox0 + 2 * jc;
        u64 v = 0ull;
        if (gr < HIN && gc < WIN)
            v = *(const u64*)&xb[(size_t)(ci * HIN + gr) * WIN + gc];
        s_pe[ci][r][jc] = v;
    }
    __syncthreads();

    // strip: pair-col jp, feat rows r0, r0+1; odd pairs built in regs
    const int jp = tid & 31;
    const int r0 = (tid >> 5) * 2;

    u64 e[CIN][3], o[CIN][3];
#pragma unroll
    for (int ci = 0; ci < CIN; ci++) {
#pragma unroll
        for (int i = 0; i < 3; i++) {
            u64 ev = s_pe[ci][r0 + i][jp];
            u64 en = s_pe[ci][r0 + i][jp + 1];
            float elo, ehi, nlo, nhi;
            up2(ev, elo, ehi); up2(en, nlo, nhi);
            e[ci][i] = ev;
            o[ci][i] = pk2(ehi, nlo);
        }
    }

    float accA[2], accB[2];
    accA[0] = accA[1] = accB[0] = accB[1] = 0.f;

#pragma unroll 1
    for (int c = 0; c < COUT; c++) {
        const u64* w = &c_all[c * CSTR];      // warp-uniform -> LDCU/UR
        const u64 sh = w[NTAP];
#pragma unroll
        for (int i = 0; i < 2; i++) {
            u64 v0 = fma2(w[0], e[0][i], sh);       // shift folded into chain init
            v0 = fma2(w[1],  o[0][i],     v0);
            v0 = fma2(w[2],  e[0][i + 1], v0);
            v0 = fma2(w[3],  o[0][i + 1], v0);
            v0 = fma2(w[4],  e[1][i],     v0);
            v0 = fma2(w[5],  o[1][i],     v0);
            u64 v1 = mul2(w[6], e[1][i + 1]);
            v1 = fma2(w[7],  o[1][i + 1], v1);
            v1 = fma2(w[8],  e[2][i],     v1);
            v1 = fma2(w[9],  o[2][i],     v1);
            v1 = fma2(w[10], e[2][i + 1], v1);
            v1 = fma2(w[11], o[2][i + 1], v1);
            u64 v = add2(v0, v1);
            float lo, hi; up2(v, lo, hi);
            accA[i] += tha(fmaxf(lo, 0.f));
            accB[i] += tha(fmaxf(hi, 0.f));
        }
    }
    s_st[r0 + 0][jp] = pk2(accA[0], accB[0]);
    s_st[r0 + 1][jp] = pk2(accA[1], accB[1]);
    __syncthreads();

    // 2x2 window mean (float view, row stride 66)
    const float* stf = (const float*)s_st;
    const float inv = 1.0f / (COUT * KSZ * KSZ);
    for (int p = tid; p < 62 * 15; p += 256) {
        const int oy = p / 62, ox_ = p - oy * 62;
        const int oi = oy0 + oy, oj = ox0 + ox_;
        if (oi < HO && oj < WO) {
            const float* rp = stf + oy * 66 + ox_;
            out[(size_t)(b * HO + oi) * WO + oj] =
                (rp[0] + rp[1] + rp[66] + rp[67]) * inv;
        }
    }
}

// ---------------------------------------------------------------------------
// kernel_launch: inputs: x, conv_w, conv_b (cancels under BN), gamma, beta
// ---------------------------------------------------------------------------
extern "C" void kernel_launch(void* const* d_in, const int* in_sizes, int n_in,
                              void* d_out, int out_size) {
    const float* x      = (const float*)d_in[0];
    const float* conv_w = (const float*)d_in[1];
    const float* gamma  = (const float*)d_in[3];
    const float* beta   = (const float*)d_in[4];
    float* out = (float*)d_out;

    void* p_all = 0;
    cudaGetSymbolAddress(&p_all, g_all);

    prep_kernel<<<1, 96>>>();
    stats_kernel<<<592, 256>>>(x);
    finalize_kernel<<<1, COUT>>>(conv_w, gamma, beta);
    cudaMemcpyToSymbolAsync(c_all, p_all, COUT * CSTR * sizeof(u64),
                            0, cudaMemcpyDeviceToDevice, 0);

    dim3 grid(5, 17, BATCH);   // 62-wide x 15-tall output tiles
    fused_out_kernel<<<grid, 256>>>(x, out);
}